// round 4
// baseline (speedup 1.0000x reference)
#include <cuda_runtime.h>
#include <cuda_bf16.h>
#include <cstdint>

// out = X @ W_eff^T + bias, W_eff = W + 2*B@A
// bf16 split-precision GEMM via mma.sync (base sm_103 target).
// X is cp.async'd as fp32; A-fragments (hi + lo residual) built in registers.
// W pre-split into bf16 hi/lo by a prep kernel; 3-stage cp.async pipeline.

#define M_TOTAL 16384
#define N_DIM   1024
#define K_DIM   1024
#define R_RANK  16

#define BM 128
#define BN 128
#define BK 64
#define NCHUNK (K_DIM / BK)   // 16

// stage layout (bytes): X fp32 128x64 (32KB), Whi/Wlo bf16 128x64 (16KB each)
#define STG_X   0
#define STG_WHI 32768
#define STG_WLO 49152
#define STAGE_BYTES 65536
#define NSTAGE 3
#define SMEM_BYTES (NSTAGE * STAGE_BYTES)   // 192KB

__device__ __nv_bfloat16 g_Whi[N_DIM * K_DIM];
__device__ __nv_bfloat16 g_Wlo[N_DIM * K_DIM];

// ---------------- PTX helpers ----------------
__device__ __forceinline__ uint32_t smem_u32(const void* p) {
    uint32_t a;
    asm("{ .reg .u64 t; cvta.to.shared.u64 t, %1; cvt.u32.u64 %0, t; }" : "=r"(a) : "l"(p));
    return a;
}

#define CP_ASYNC16(dst, src) \
    asm volatile("cp.async.cg.shared.global [%0], [%1], 16;" :: "r"(dst), "l"(src))
#define CP_COMMIT() asm volatile("cp.async.commit_group;" ::: "memory")
#define CP_WAIT1()  asm volatile("cp.async.wait_group 1;" ::: "memory")
#define CP_WAIT0()  asm volatile("cp.async.wait_group 0;" ::: "memory")

#define LDSM_X4(r0, r1, r2, r3, addr) \
    asm volatile("ldmatrix.sync.aligned.m8n8.x4.shared.b16 {%0,%1,%2,%3}, [%4];" \
                 : "=r"(r0), "=r"(r1), "=r"(r2), "=r"(r3) : "r"(addr))

#define MMA_BF16(d, a, b) \
    asm volatile("mma.sync.aligned.m16n8k16.row.col.f32.bf16.bf16.f32 " \
                 "{%0,%1,%2,%3}, {%4,%5,%6,%7}, {%8,%9}, {%0,%1,%2,%3};" \
                 : "+f"((d)[0]), "+f"((d)[1]), "+f"((d)[2]), "+f"((d)[3]) \
                 : "r"((a)[0]), "r"((a)[1]), "r"((a)[2]), "r"((a)[3]), \
                   "r"((b)[0]), "r"((b)[1]))

// pack bf16x2 {low=l, high=h}
__device__ __forceinline__ uint32_t cvt2bf16(float l, float h) {
    uint32_t r;
    asm("cvt.rn.bf16x2.f32 %0, %1, %2;" : "=r"(r) : "f"(h), "f"(l));
    return r;
}

__device__ __forceinline__ void split4(float4 v, uint32_t& hi01, uint32_t& hi23,
                                       uint32_t& lo01, uint32_t& lo23) {
    hi01 = cvt2bf16(v.x, v.y);
    hi23 = cvt2bf16(v.z, v.w);
    float h0 = __uint_as_float(hi01 << 16), h1 = __uint_as_float(hi01 & 0xffff0000u);
    float h2 = __uint_as_float(hi23 << 16), h3 = __uint_as_float(hi23 & 0xffff0000u);
    lo01 = cvt2bf16(v.x - h0, v.y - h1);
    lo23 = cvt2bf16(v.z - h2, v.w - h3);
}

// X tile smem addr for logical (row, col) float; 16-chunk XOR swizzle per row
__device__ __forceinline__ uint32_t xaddr(uint32_t xbuf, int row, int col) {
    return xbuf + (uint32_t)(row * 256) +
           (uint32_t)((((col >> 2) ^ row) & 15) << 4) + (uint32_t)((col & 3) << 2);
}

// ---------------------------------------------------------------------------
// Prep: W_eff = W + 2*B@A, split bf16 hi/lo.
// ---------------------------------------------------------------------------
__global__ void build_weff_split_kernel(const float* __restrict__ W,
                                        const float* __restrict__ A,
                                        const float* __restrict__ Bm) {
    const int o = blockIdx.x;
    const int t = threadIdx.x;
    __shared__ float brow[R_RANK];
    if (t < R_RANK) brow[t] = 2.0f * Bm[o * R_RANK + t];
    __syncthreads();

    for (int k4 = t * 4; k4 < K_DIM; k4 += blockDim.x * 4) {
        float4 w = *(const float4*)&W[o * K_DIM + k4];
        float v[4] = {w.x, w.y, w.z, w.w};
        #pragma unroll
        for (int r = 0; r < R_RANK; r++) {
            float br = brow[r];
            const float4 a = *(const float4*)&A[r * K_DIM + k4];
            v[0] = fmaf(br, a.x, v[0]); v[1] = fmaf(br, a.y, v[1]);
            v[2] = fmaf(br, a.z, v[2]); v[3] = fmaf(br, a.w, v[3]);
        }
        uint32_t hi01, hi23, lo01, lo23;
        split4(make_float4(v[0], v[1], v[2], v[3]), hi01, hi23, lo01, lo23);
        *(uint2*)&g_Whi[o * K_DIM + k4] = make_uint2(hi01, hi23);
        *(uint2*)&g_Wlo[o * K_DIM + k4] = make_uint2(lo01, lo23);
    }
}

// ---------------------------------------------------------------------------
// Main GEMM: 128x128 CTA, 512 threads, warp tile 32x32, bf16 split (3 mma),
// fp32 X staged in smem, A-fragments converted in registers.
// ---------------------------------------------------------------------------
__global__ __launch_bounds__(512) void lora_gemm_mma_kernel(
    const float* __restrict__ X,
    const float* __restrict__ bias,
    float* __restrict__ Out) {
    extern __shared__ char smem[];
    const uint32_t sbase = smem_u32(smem);
    const int tid = threadIdx.x;
    const int lane = tid & 31;
    const int wid = tid >> 5;          // 0..15
    const int wm = wid & 3;            // 4 warps along M
    const int wn = wid >> 2;           // 4 warps along N

    const int block_m = blockIdx.y * BM;
    const int block_n = blockIdx.x * BN;

    // ---- cp.async plan: 8 x 16B chunks/thread/stage.
    // i=0..3 -> X fp32 (2048 chunks), i=4,5 -> Whi, i=6,7 -> Wlo (1024 each)
    uint32_t cp_dst[8];
    const char* cp_src[8];
    #pragma unroll
    for (int i = 0; i < 4; i++) {
        int idx = tid + i * 512;           // 0..2047
        int r = idx >> 4, c16 = idx & 15;
        cp_dst[i] = sbase + STG_X + (uint32_t)(r * 256 + ((c16 ^ (r & 15)) << 4));
        cp_src[i] = (const char*)(X + (size_t)(block_m + r) * K_DIM + c16 * 4);
    }
    #pragma unroll
    for (int i = 4; i < 8; i++) {
        int j = tid + (i - 4) * 512;       // 0..2047
        int whichlo = j >> 10;             // 0:Whi 1:Wlo
        int r = (j & 1023) >> 3, c16 = j & 7;
        uint32_t off = (whichlo ? STG_WLO : STG_WHI) +
                       (uint32_t)(r * 128 + ((c16 ^ (r & 7)) << 4));
        const __nv_bfloat16* g = whichlo ? g_Wlo : g_Whi;
        cp_dst[i] = sbase + off;
        cp_src[i] = (const char*)(g + (size_t)(block_n + r) * K_DIM + c16 * 8);
    }

    // per-chunk source step: X rows advance 64 floats (256B), W rows 64 bf16 (128B)
    #define CP_STEP(i) ((i) < 4 ? BK * 4 : BK * 2)

    // ---- fragment address components ----
    const int arow = lane >> 2;               // 0..7
    const int acol = (lane & 3) * 2;          // 0,2,4,6
    const int b_row = wn * 32 + (lane & 7) + ((lane >> 4) & 1) * 8;
    const uint32_t b_swz = (uint32_t)((b_row & 7) * 16);
    const int b_khalf = ((lane >> 3) & 1) * 16;

    float acc[2][4][4];
    #pragma unroll
    for (int mf = 0; mf < 2; mf++)
        #pragma unroll
        for (int nf = 0; nf < 4; nf++)
            #pragma unroll
            for (int r = 0; r < 4; r++)
                acc[mf][nf][r] = 0.0f;

    // prologue: stages 0 and 1
    #pragma unroll
    for (int i = 0; i < 8; i++) CP_ASYNC16(cp_dst[i], cp_src[i]);
    CP_COMMIT();
    #pragma unroll
    for (int i = 0; i < 8; i++) CP_ASYNC16(cp_dst[i] + STAGE_BYTES, cp_src[i] + CP_STEP(i));
    CP_COMMIT();

    for (int c = 0; c < NCHUNK; c++) {
        if (c + 1 < NCHUNK) CP_WAIT1(); else CP_WAIT0();
        __syncthreads();

        if (c + 2 < NCHUNK) {
            const uint32_t stg = (uint32_t)(((c + 2) % NSTAGE) * STAGE_BYTES);
            #pragma unroll
            for (int i = 0; i < 8; i++)
                CP_ASYNC16(cp_dst[i] + stg, cp_src[i] + (c + 2) * CP_STEP(i));
            CP_COMMIT();
        }

        const uint32_t buf = sbase + (uint32_t)((c % NSTAGE) * STAGE_BYTES);
        const uint32_t xbuf = buf + STG_X;

        #pragma unroll
        for (int ks = 0; ks < 4; ks++) {
            uint32_t ahi[2][4], alo[2][4], bhi[4][2], blo[4][2];
            const int col0 = acol + ks * 16;

            // A fragments: fp32 smem -> bf16 hi + lo residual, in mma layout.
            // j order: (r,k0),(r+8,k0),(r,k0+8),(r+8,k0+8)
            #pragma unroll
            for (int mf = 0; mf < 2; mf++) {
                const int rbase = wm * 32 + mf * 16 + arow;
                #pragma unroll
                for (int j = 0; j < 4; j++) {
                    const int row = rbase + (j & 1) * 8;
                    const int col = col0 + (j >> 1) * 8;
                    float fx, fy;
                    asm volatile("ld.shared.v2.f32 {%0,%1}, [%2];"
                                 : "=f"(fx), "=f"(fy) : "r"(xaddr(xbuf, row, col)));
                    uint32_t hi = cvt2bf16(fx, fy);
                    float hx = __uint_as_float(hi << 16);
                    float hy = __uint_as_float(hi & 0xffff0000u);
                    ahi[mf][j] = hi;
                    alo[mf][j] = cvt2bf16(fx - hx, fy - hy);
                }
            }
            // B fragments via ldmatrix (bf16 hi/lo tiles)
            const uint32_t bkb = (uint32_t)(ks * 32 + b_khalf) ^ b_swz;
            #pragma unroll
            for (int np = 0; np < 2; np++) {
                const uint32_t bo = (uint32_t)((b_row + np * 16) * 128) + bkb;
                LDSM_X4(bhi[np * 2][0], bhi[np * 2][1], bhi[np * 2 + 1][0], bhi[np * 2 + 1][1],
                        buf + STG_WHI + bo);
                LDSM_X4(blo[np * 2][0], blo[np * 2][1], blo[np * 2 + 1][0], blo[np * 2 + 1][1],
                        buf + STG_WLO + bo);
            }
            #pragma unroll
            for (int mf = 0; mf < 2; mf++)
                #pragma unroll
                for (int nf = 0; nf < 4; nf++) {
                    MMA_BF16(acc[mf][nf], ahi[mf], bhi[nf]);
                    MMA_BF16(acc[mf][nf], ahi[mf], blo[nf]);
                    MMA_BF16(acc[mf][nf], alo[mf], bhi[nf]);
                }
        }
        // no trailing sync: next iteration's wait+sync orders buffer reuse
    }

    // ---- epilogue: direct global stores + bias ----
    const int mrow = block_m + wm * 32 + (lane >> 2);
    const int ncol = block_n + wn * 32 + 2 * (lane & 3);
    #pragma unroll
    for (int mf = 0; mf < 2; mf++) {
        #pragma unroll
        for (int nf = 0; nf < 4; nf++) {
            const int n = ncol + nf * 8;
            const float2 bv = *(const float2*)&bias[n];
            const int r0 = mrow + mf * 16;
            float2 o0 = make_float2(acc[mf][nf][0] + bv.x, acc[mf][nf][1] + bv.y);
            float2 o1 = make_float2(acc[mf][nf][2] + bv.x, acc[mf][nf][3] + bv.y);
            *(float2*)&Out[(size_t)r0 * N_DIM + n] = o0;
            *(float2*)&Out[(size_t)(r0 + 8) * N_DIM + n] = o1;
        }
    }
}

// ---------------------------------------------------------------------------
extern "C" void kernel_launch(void* const* d_in, const int* in_sizes, int n_in,
                              void* d_out, int out_size) {
    const float* x  = (const float*)d_in[0];
    const float* W  = (const float*)d_in[1];
    const float* b  = (const float*)d_in[2];
    const float* A  = (const float*)d_in[3];
    const float* Bm = (const float*)d_in[4];
    float* out = (float*)d_out;

    cudaFuncSetAttribute(lora_gemm_mma_kernel,
                         cudaFuncAttributeMaxDynamicSharedMemorySize, SMEM_BYTES);

    build_weff_split_kernel<<<N_DIM, 256>>>(W, A, Bm);

    dim3 grid(N_DIM / BN, M_TOTAL / BM);   // (8, 128)
    lora_gemm_mma_kernel<<<grid, 512, SMEM_BYTES>>>(x, b, out);
}

// round 5
// speedup vs baseline: 2.2730x; 2.2730x over previous
#include <cuda_runtime.h>
#include <cuda_bf16.h>
#include <cstdint>

// out = X @ W_eff^T + bias, W_eff = W + 2*B@A
// Single-pass TF32 GEMM via mma.sync.m16n8k8 (base sm_103 target).
// W_eff pre-rounded to tf32 in prep; X cp.async'd raw fp32, A-fragments
// rounded with cvt.rna.tf32 in registers (unbiased — truncation would fail).
// Fragments loaded via ldmatrix.b16 on the b32 tile (layout matches exactly).

#define M_TOTAL 16384
#define N_DIM   1024
#define K_DIM   1024
#define R_RANK  16

#define BM 128
#define BN 128
#define BK 64
#define NCHUNK (K_DIM / BK)   // 16
#define KSTEPS (BK / 8)       // 8 k-steps of 8

// stage layout: X fp32 128x64 (32KB) + W tf32 128x64 (32KB)
#define STG_X 0
#define STG_W 32768
#define STAGE_BYTES 65536
#define NSTAGE 3
#define SMEM_BYTES (NSTAGE * STAGE_BYTES)   // 192KB

__device__ float g_Wtf[N_DIM * K_DIM];   // W_eff, tf32-rounded fp32 bits

// ---------------- PTX helpers ----------------
__device__ __forceinline__ uint32_t smem_u32(const void* p) {
    uint32_t a;
    asm("{ .reg .u64 t; cvta.to.shared.u64 t, %1; cvt.u32.u64 %0, t; }" : "=r"(a) : "l"(p));
    return a;
}

#define CP_ASYNC16(dst, src) \
    asm volatile("cp.async.cg.shared.global [%0], [%1], 16;" :: "r"(dst), "l"(src))
#define CP_COMMIT() asm volatile("cp.async.commit_group;" ::: "memory")
#define CP_WAIT1()  asm volatile("cp.async.wait_group 1;" ::: "memory")
#define CP_WAIT0()  asm volatile("cp.async.wait_group 0;" ::: "memory")

#define LDSM_X4(r0, r1, r2, r3, addr) \
    asm volatile("ldmatrix.sync.aligned.m8n8.x4.shared.b16 {%0,%1,%2,%3}, [%4];" \
                 : "=r"(r0), "=r"(r1), "=r"(r2), "=r"(r3) : "r"(addr))

#define MMA_TF32(d, a0, a1, a2, a3, b0, b1) \
    asm volatile("mma.sync.aligned.m16n8k8.row.col.f32.tf32.tf32.f32 " \
                 "{%0,%1,%2,%3}, {%4,%5,%6,%7}, {%8,%9}, {%0,%1,%2,%3};" \
                 : "+f"((d)[0]), "+f"((d)[1]), "+f"((d)[2]), "+f"((d)[3]) \
                 : "r"(a0), "r"(a1), "r"(a2), "r"(a3), "r"(b0), "r"(b1))

__device__ __forceinline__ uint32_t cvt_tf32(uint32_t x) {
    uint32_t r;
    asm("cvt.rna.tf32.f32 %0, %1;" : "=r"(r) : "r"(x));
    return r;
}

// ---------------------------------------------------------------------------
// Prep: W_eff = W + 2*B@A, rounded to tf32.
// ---------------------------------------------------------------------------
__global__ void build_weff_tf32_kernel(const float* __restrict__ W,
                                       const float* __restrict__ A,
                                       const float* __restrict__ Bm) {
    const int o = blockIdx.x;
    const int t = threadIdx.x;
    __shared__ float brow[R_RANK];
    if (t < R_RANK) brow[t] = 2.0f * Bm[o * R_RANK + t];
    __syncthreads();

    for (int k4 = t * 4; k4 < K_DIM; k4 += blockDim.x * 4) {
        float4 w = *(const float4*)&W[o * K_DIM + k4];
        float v[4] = {w.x, w.y, w.z, w.w};
        #pragma unroll
        for (int r = 0; r < R_RANK; r++) {
            float br = brow[r];
            const float4 a = *(const float4*)&A[r * K_DIM + k4];
            v[0] = fmaf(br, a.x, v[0]); v[1] = fmaf(br, a.y, v[1]);
            v[2] = fmaf(br, a.z, v[2]); v[3] = fmaf(br, a.w, v[3]);
        }
        uint4 o4;
        o4.x = cvt_tf32(__float_as_uint(v[0]));
        o4.y = cvt_tf32(__float_as_uint(v[1]));
        o4.z = cvt_tf32(__float_as_uint(v[2]));
        o4.w = cvt_tf32(__float_as_uint(v[3]));
        *(uint4*)&g_Wtf[o * K_DIM + k4] = o4;
    }
}

// ---------------------------------------------------------------------------
// Main GEMM: 128x128 CTA, 512 threads, warp tile 32x32, single-pass tf32.
// ---------------------------------------------------------------------------
__global__ __launch_bounds__(512) void lora_gemm_tf32_kernel(
    const float* __restrict__ X,
    const float* __restrict__ bias,
    float* __restrict__ Out) {
    extern __shared__ char smem[];
    const uint32_t sbase = smem_u32(smem);
    const int tid = threadIdx.x;
    const int lane = tid & 31;
    const int wid = tid >> 5;          // 0..15
    const int wm = wid & 3;            // 4 warps along M (32 rows)
    const int wn = wid >> 2;           // 4 warps along N (32 cols)

    const int block_m = blockIdx.y * BM;
    const int block_n = blockIdx.x * BN;

    // ---- cp.async plan: 8 x 16B chunks/thread/stage (X 2048 + W 2048) ----
    uint32_t cp_dst[8];
    const char* cp_src[8];
    #pragma unroll
    for (int i = 0; i < 8; i++) {
        int idx = tid + (i & 3) * 512;     // 0..2047
        int r = idx >> 4, c16 = idx & 15;  // row 0..127, 16B chunk 0..15
        uint32_t off = (uint32_t)(r * 256 + ((c16 ^ (r & 15)) << 4));
        if (i < 4) {
            cp_dst[i] = sbase + STG_X + off;
            cp_src[i] = (const char*)(X + (size_t)(block_m + r) * K_DIM + c16 * 4);
        } else {
            cp_dst[i] = sbase + STG_W + off;
            cp_src[i] = (const char*)(g_Wtf + (size_t)(block_n + r) * K_DIM + c16 * 4);
        }
    }
    // every chunk advances 64 floats = 256B in K

    // ---- ldmatrix row/swizzle components (b32 tile viewed as b16 pairs) ----
    // x4: lanes 0-7 mat0(rows+0,k0-3) 8-15 mat1(rows+8) 16-23 mat2(k+4) 24-31 mat3
    const int arow_l = (lane & 7) + ((lane >> 3) & 1) * 8;  // row within 16-block
    const int khalf  = (lane >> 4) & 1;                      // chunk +0 / +1

    float acc[2][4][4];
    #pragma unroll
    for (int mf = 0; mf < 2; mf++)
        #pragma unroll
        for (int nf = 0; nf < 4; nf++)
            #pragma unroll
            for (int r = 0; r < 4; r++)
                acc[mf][nf][r] = 0.0f;

    // prologue: stages 0, 1
    #pragma unroll
    for (int i = 0; i < 8; i++) CP_ASYNC16(cp_dst[i], cp_src[i]);
    CP_COMMIT();
    #pragma unroll
    for (int i = 0; i < 8; i++) CP_ASYNC16(cp_dst[i] + STAGE_BYTES, cp_src[i] + BK * 4);
    CP_COMMIT();

    for (int c = 0; c < NCHUNK; c++) {
        if (c + 1 < NCHUNK) CP_WAIT1(); else CP_WAIT0();
        __syncthreads();

        if (c + 2 < NCHUNK) {
            const uint32_t stg = (uint32_t)(((c + 2) % NSTAGE) * STAGE_BYTES);
            #pragma unroll
            for (int i = 0; i < 8; i++)
                CP_ASYNC16(cp_dst[i] + stg, cp_src[i] + (c + 2) * BK * 4);
            CP_COMMIT();
        }

        const uint32_t buf = sbase + (uint32_t)((c % NSTAGE) * STAGE_BYTES);

        #pragma unroll
        for (int ks = 0; ks < KSTEPS; ks++) {
            const int kchunk = ks * 2 + khalf;
            uint32_t a[2][4], b[2][4];
            // A fragments: 2 m-halves of the 32-row warp tile
            #pragma unroll
            for (int mf = 0; mf < 2; mf++) {
                const int row = wm * 32 + mf * 16 + arow_l;
                const uint32_t ao = buf + STG_X +
                    (uint32_t)(row * 256 + ((kchunk ^ (row & 15)) << 4));
                LDSM_X4(a[mf][0], a[mf][1], a[mf][2], a[mf][3], ao);
                a[mf][0] = cvt_tf32(a[mf][0]);
                a[mf][1] = cvt_tf32(a[mf][1]);
                a[mf][2] = cvt_tf32(a[mf][2]);
                a[mf][3] = cvt_tf32(a[mf][3]);
            }
            // B fragments: 2 n-16-blocks (regs: r0=(n+0,k0-3) r1=(n+8,k0-3)
            //                                     r2=(n+0,k4-7) r3=(n+8,k4-7))
            #pragma unroll
            for (int np = 0; np < 2; np++) {
                const int row = wn * 32 + np * 16 + arow_l;
                const uint32_t bo = buf + STG_W +
                    (uint32_t)(row * 256 + ((kchunk ^ (row & 15)) << 4));
                LDSM_X4(b[np][0], b[np][1], b[np][2], b[np][3], bo);
            }
            #pragma unroll
            for (int mf = 0; mf < 2; mf++)
                #pragma unroll
                for (int nf = 0; nf < 4; nf++) {
                    const int np = nf >> 1, h = nf & 1;
                    MMA_TF32(acc[mf][nf], a[mf][0], a[mf][1], a[mf][2], a[mf][3],
                             b[np][h], b[np][h + 2]);
                }
        }
        // buffer reuse ordered by next iteration's wait + syncthreads
    }

    // ---- epilogue: bias + direct stores ----
    const int mrow = block_m + wm * 32 + (lane >> 2);
    const int ncol = block_n + wn * 32 + 2 * (lane & 3);
    #pragma unroll
    for (int mf = 0; mf < 2; mf++) {
        #pragma unroll
        for (int nf = 0; nf < 4; nf++) {
            const int n = ncol + nf * 8;
            const float2 bv = *(const float2*)&bias[n];
            const int r0 = mrow + mf * 16;
            float2 o0 = make_float2(acc[mf][nf][0] + bv.x, acc[mf][nf][1] + bv.y);
            float2 o1 = make_float2(acc[mf][nf][2] + bv.x, acc[mf][nf][3] + bv.y);
            *(float2*)&Out[(size_t)r0 * N_DIM + n] = o0;
            *(float2*)&Out[(size_t)(r0 + 8) * N_DIM + n] = o1;
        }
    }
}

// ---------------------------------------------------------------------------
extern "C" void kernel_launch(void* const* d_in, const int* in_sizes, int n_in,
                              void* d_out, int out_size) {
    const float* x  = (const float*)d_in[0];
    const float* W  = (const float*)d_in[1];
    const float* b  = (const float*)d_in[2];
    const float* A  = (const float*)d_in[3];
    const float* Bm = (const float*)d_in[4];
    float* out = (float*)d_out;

    cudaFuncSetAttribute(lora_gemm_tf32_kernel,
                         cudaFuncAttributeMaxDynamicSharedMemorySize, SMEM_BYTES);

    build_weff_tf32_kernel<<<N_DIM, 256>>>(W, A, Bm);

    dim3 grid(N_DIM / BN, M_TOTAL / BM);   // (8, 128)
    lora_gemm_tf32_kernel<<<grid, 512, SMEM_BYTES>>>(x, b, out);
}